// round 17
// baseline (speedup 1.0000x reference)
#include <cuda_runtime.h>
#include <cuda_fp16.h>
#include <math.h>
#include <stdint.h>

#define B_  4
#define T_  2048
#define C_  768
#define H_  8
#define HS_ 96
#define M_  (B_*T_)     // 8192
#define C3_ (3*C_)      // 2304

#define SCALE2F 0.14724444f   // (1/sqrt(96)) * log2(e)

// ---------------------------------------------------------------------------
// Device-global scratch (pure fp16; q pre-scaled by SCALE2F)
// ---------------------------------------------------------------------------
__device__ __half g_q[(size_t)B_*H_*T_*HS_];
__device__ __half g_k[(size_t)B_*H_*T_*HS_];
__device__ __half g_v[(size_t)B_*H_*T_*HS_];
__device__ __half g_x[(size_t)M_*C_];
__device__ __half g_y[(size_t)M_*C_];
__device__ __half g_wah[(size_t)C3_*C_];   // [N][K]
__device__ __half g_wph[(size_t)C_*C_];    // [N][K]

// ---------------------------------------------------------------------------
// PTX helpers
// ---------------------------------------------------------------------------
__device__ __forceinline__ uint32_t cvta_smem(const void* p) {
    uint32_t a;
    asm("{ .reg .u64 t; cvta.to.shared.u64 t, %1; cvt.u32.u64 %0, t; }"
        : "=r"(a) : "l"(p));
    return a;
}

#define CP16(dst, src) \
    asm volatile("cp.async.cg.shared.global [%0], [%1], 16;" \
                 :: "r"(dst), "l"(src) : "memory")
#define CP_COMMIT() asm volatile("cp.async.commit_group;" ::: "memory")
#define CP_WAIT1()  asm volatile("cp.async.wait_group 1;" ::: "memory")
#define CP_WAIT0()  asm volatile("cp.async.wait_group 0;" ::: "memory")

#define MBAR_INIT(addr, cnt) \
    asm volatile("mbarrier.init.shared.b64 [%0], %1;" :: "r"(addr), "r"(cnt) : "memory")
#define MBAR_ARRIVE(addr) \
    asm volatile("mbarrier.arrive.shared.b64 _, [%0];" :: "r"(addr) : "memory")
#define CPMB_ARRIVE(addr) \
    asm volatile("cp.async.mbarrier.arrive.noinc.shared.b64 [%0];" :: "r"(addr) : "memory")

#define MBAR_WAIT(addr, parity) do {                                          \
    uint32_t _m = (addr); uint32_t _p = (parity); uint32_t _done;             \
    asm volatile("{\n\t.reg .pred p;\n\t"                                     \
        "mbarrier.try_wait.parity.acquire.cta.shared::cta.b64 p, [%1], %2;\n\t" \
        "selp.b32 %0, 1, 0, p;\n\t}" : "=r"(_done) : "r"(_m), "r"(_p) : "memory"); \
    if (!_done) {                                                             \
        asm volatile("{\n\t.reg .pred P1;\n\t"                                \
            "W_%=:\n\t"                                                       \
            "mbarrier.try_wait.parity.acquire.cta.shared::cta.b64 P1, [%0], %1, 0x989680;\n\t" \
            "@P1 bra.uni D_%=;\n\t"                                           \
            "bra.uni W_%=;\n\t"                                               \
            "D_%=:\n\t}" :: "r"(_m), "r"(_p) : "memory");                     \
    }                                                                         \
} while (0)

__device__ __forceinline__ void ldm4(uint32_t* r, uint32_t addr) {
    asm volatile("ldmatrix.sync.aligned.m8n8.x4.shared.b16 {%0,%1,%2,%3}, [%4];"
                 : "=r"(r[0]), "=r"(r[1]), "=r"(r[2]), "=r"(r[3]) : "r"(addr));
}
__device__ __forceinline__ void ldm4t(uint32_t* r, uint32_t addr) {
    asm volatile("ldmatrix.sync.aligned.m8n8.x4.trans.shared.b16 {%0,%1,%2,%3}, [%4];"
                 : "=r"(r[0]), "=r"(r[1]), "=r"(r[2]), "=r"(r[3]) : "r"(addr));
}

__device__ __forceinline__ void mma16816(float* d, const uint32_t* a, const uint32_t* b) {
    asm volatile(
        "mma.sync.aligned.m16n8k16.row.col.f32.f16.f16.f32 "
        "{%0,%1,%2,%3}, {%4,%5,%6,%7}, {%8,%9}, {%0,%1,%2,%3};"
        : "+f"(d[0]), "+f"(d[1]), "+f"(d[2]), "+f"(d[3])
        : "r"(a[0]), "r"(a[1]), "r"(a[2]), "r"(a[3]), "r"(b[0]), "r"(b[1]));
}

// pack (lo, hi) into f16x2 and take 2^x of both halves — 2 SASS instructions
__device__ __forceinline__ uint32_t pex2(float lo, float hi) {
    uint32_t t, d;
    asm("cvt.rn.f16x2.f32 %0, %1, %2;" : "=r"(t) : "f"(hi), "f"(lo));
    asm("ex2.approx.f16x2 %0, %1;" : "=r"(d) : "r"(t));
    return d;
}

// ---------------------------------------------------------------------------
// Single fused convert kernel (validated R15)
// ---------------------------------------------------------------------------
#define XBLK 1536
#define WBX  96
#define WBLK (WBX*24)

__global__ __launch_bounds__(256) void cvt_all(const float* __restrict__ x,
                                               const float* __restrict__ Wa,
                                               const float* __restrict__ Wp)
{
    int b = blockIdx.x;
    if (b < XBLK) {
        size_t i = ((size_t)b * 256 + threadIdx.x) * 16;
#pragma unroll
        for (int j = 0; j < 4; j++) {
            float4 v = *(const float4*)(x + i + j*4);
            *(__half2*)(g_x + i + j*4)     = __halves2half2(__float2half_rn(v.x), __float2half_rn(v.y));
            *(__half2*)(g_x + i + j*4 + 2) = __halves2half2(__float2half_rn(v.z), __float2half_rn(v.w));
        }
    } else {
        b -= XBLK;
        int bx = b % WBX;
        const int by = b / WBX;
        __shared__ float t[32][33];
        const float* Wm; __half* Th; int N;
        if (bx < C3_/32) { Wm = Wa; Th = g_wah; N = C3_; }
        else             { bx -= C3_/32; Wm = Wp; Th = g_wph; N = C_; }
        const int tx = threadIdx.x & 31;
        const int ty = threadIdx.x >> 5;
#pragma unroll
        for (int r = 0; r < 4; r++) {
            const int kl = ty + r*8;
            t[kl][tx] = Wm[(size_t)(by*32 + kl) * N + bx*32 + tx];
        }
        __syncthreads();
#pragma unroll
        for (int r = 0; r < 4; r++) {
            const int nl = ty + r*8;
            Th[(size_t)(bx*32 + nl) * C_ + by*32 + tx] = __float2half_rn(t[tx][nl]);
        }
    }
}

// ---------------------------------------------------------------------------
// Warp-MMA fp16 GEMM. CTA 128 x NT (NT=128 for QKV, 64 for proj to smooth
// wave quantization). 8 warps (4 along M, 2 along N), KC=64, 2-stage,
// 2 CTAs/SM. Q output pre-scaled by SCALE2F.
// ---------------------------------------------------------------------------
#define KC 64
#define NCH (C_/KC)          // 12
#define GSTR 144
#define ATILE_B (128*GSTR)   // 18432 (A tile bytes)

template<int NT>
__device__ __forceinline__ void issue_chunk(
    uint32_t sbase, int s,
    const __half* __restrict__ A, const __half* __restrict__ Bm,
    int bm, int bn, int k0, int tid)
{
    const int STG = (128 + NT) * GSTR;
    const int row = tid >> 3;
    const int seg = tid & 7;
    const uint32_t dst0 = sbase + s * STG + row * GSTR + seg * 16;
    const int ke = k0 + seg * 8;
#pragma unroll
    for (int g = 0; g < 4; g++) {
        const int rr = row + g * 32;
        CP16(dst0 + g * 32 * GSTR, A + (size_t)(bm + rr) * C_ + ke);
    }
#pragma unroll
    for (int g = 0; g < NT/32; g++) {
        const int rr = row + g * 32;
        CP16(dst0 + ATILE_B + g * 32 * GSTR, Bm + (size_t)(bn + rr) * C_ + ke);
    }
    CP_COMMIT();
}

template<int MODE>
__global__ __launch_bounds__(256, 2) void gemm_mma(const float* __restrict__ bias,
                                                   float* __restrict__ out)
{
    constexpr int NT  = (MODE == 0) ? 128 : 64;   // CTA N-tile
    constexpr int NFR = NT / 16;                  // n8-frags per warp (8 / 4)
    constexpr int STG = (128 + NT) * GSTR;

    extern __shared__ char dsm[];
    const uint32_t sbase = cvta_smem(dsm);
    const int tid  = threadIdx.x;
    const int wid  = tid >> 5;
    const int lane = tid & 31;
    const int wm = wid & 3;
    const int wn = wid >> 2;
    const int bn = blockIdx.x * NT;
    const int bm = blockIdx.y * 128;

    const __half *A  = (MODE == 0) ? g_x  : g_y;
    const __half *Bm = (MODE == 0) ? g_wah : g_wph;

    float acc[2][NFR][4];
#pragma unroll
    for (int mi = 0; mi < 2; mi++)
#pragma unroll
        for (int ni = 0; ni < NFR; ni++)
#pragma unroll
            for (int j = 0; j < 4; j++) acc[mi][ni][j] = 0.f;

    const int arow = lane & 15;
    const int akh  = (lane >> 4) << 3;
    const int brow = (lane & 7) + ((lane >> 4) << 3);
    const int bkh  = ((lane >> 3) & 1) << 3;

    issue_chunk<NT>(sbase, 0, A, Bm, bm, bn, 0, tid);

    for (int c = 0; c < NCH; ++c) {
        const int s = c & 1;
        if (c + 1 < NCH) {
            issue_chunk<NT>(sbase, s ^ 1, A, Bm, bm, bn, (c + 1) * KC, tid);
            CP_WAIT1();
        } else {
            CP_WAIT0();
        }
        __syncthreads();

        const uint32_t base = sbase + s * STG;
#pragma unroll
        for (int kk = 0; kk < KC; kk += 16) {
            uint32_t ah[2][4];
#pragma unroll
            for (int mi = 0; mi < 2; mi++) {
                uint32_t ra = base + (wm*32 + mi*16 + arow) * GSTR + (kk + akh) * 2;
                ldm4(ah[mi], ra);
            }
#pragma unroll
            for (int nt = 0; nt < NT/32; nt++) {
                const uint32_t rb = base + ATILE_B + (wn*(NT/2) + nt*16 + brow) * GSTR + (kk + bkh) * 2;
                uint32_t u[4];
                ldm4(u, rb);
                mma16816(acc[0][2*nt],   ah[0], u);
                mma16816(acc[0][2*nt+1], ah[0], u+2);
                mma16816(acc[1][2*nt],   ah[1], u);
                mma16816(acc[1][2*nt+1], ah[1], u+2);
            }
        }
        __syncthreads();
    }

#pragma unroll
    for (int ni = 0; ni < NFR; ni++) {
        const int col = bn + wn*(NT/2) + ni*8 + (lane & 3)*2;
        const float2 bv = *(const float2*)(bias + col);
#pragma unroll
        for (int mi = 0; mi < 2; mi++) {
            const int r0 = bm + wm*32 + mi*16 + (lane >> 2);
#pragma unroll
            for (int half_ = 0; half_ < 2; half_++) {
                const int r = r0 + half_ * 8;
                float v0 = acc[mi][ni][half_*2+0] + bv.x;
                float v1 = acc[mi][ni][half_*2+1] + bv.y;
                if (MODE == 1) {
                    *(float2*)(out + (size_t)r * C_ + col) = make_float2(v0, v1);
                } else {
                    const int bb2 = r >> 11;
                    const int t   = r & (T_ - 1);
                    const int which = col / C_;
                    const int cc = col - which * C_;
                    const int h  = cc / HS_;
                    const int d  = cc - h * HS_;
                    const size_t adr = ((size_t)(bb2*H_ + h)*T_ + t)*HS_ + d;
                    if (which == 0) { v0 *= SCALE2F; v1 *= SCALE2F; }
                    __half* dst = (which == 0) ? g_q : (which == 1) ? g_k : g_v;
                    *(__half2*)(dst + adr) =
                        __halves2half2(__float2half_rn(v0), __float2half_rn(v1));
                }
            }
        }
    }
}

#define GEMM_SMEM0 (2*(128+128)*GSTR)   // 73728
#define GEMM_SMEM1 (2*(128+64)*GSTR)    // 55296

// ---------------------------------------------------------------------------
// fp16 flash attention (validated R16). BQ=256 (512 thr, 16 warps, 1 CTA/SM),
// BK=128, fixed-base softmax (f16x2 exp), l via constant ones-fragment MMA.
// NSTAGE=3, PDIST=2. K stride 208B, V stride 240B (stage-0 col 96 = 1.0h).
// ---------------------------------------------------------------------------
#define BQ 256
#define NW 16
#define ATHR (NW*32)             // 512
#define BK 128
#define KSTRB 208
#define VSTRB 240
#define KTB (128*KSTRB)          // 26624
#define VTB (128*VSTRB)          // 30720
#define ASTAGE (KTB+VTB)         // 57344
#define NSTAGE 3
#define PDIST (NSTAGE-1)         // 2
#define ATT_SMEM (NSTAGE*ASTAGE + 80)   // 172112

__device__ __forceinline__ void att_seg(uint32_t sbase, int st, size_t gro_base,
                                        int idx)
{
    const int half = (idx >= 1536);
    const int loc  = half ? idx - 1536 : idx;
    const int r    = loc / 12;
    const int seg  = loc - r * 12;
    const __half* src = (half ? g_v : g_k) + gro_base + (size_t)r * HS_ + seg * 8;
    const uint32_t dst = sbase + st * ASTAGE +
                         (half ? KTB + r * VSTRB : r * KSTRB) + seg * 16;
    CP16(dst, src);
}

__device__ __forceinline__ void issue_att_nb(uint32_t sbase, int st, size_t gbase,
                                             int j0, int tid)
{
    const size_t gro = gbase + (size_t)j0 * HS_;
#pragma unroll
    for (int i = 0; i < 6; i++)
        att_seg(sbase, st, gro, tid + i * ATHR);
}

__device__ __forceinline__ void consume64(
    uint32_t kbase, uint32_t vbase, int j0e,
    int wbase, int grow0, int grow1,
    int lane, int brow, int bkh, int jrow0, int dhalf,
    const uint32_t (*qa)[4], const uint32_t* tvONE, float (*o)[4])
{
    if (j0e > wbase + 15) return;
    const bool needmask = (j0e + 63 > wbase);

    float sf0[4][4];
#pragma unroll
    for (int i = 0; i < 4; i++)
#pragma unroll
        for (int j = 0; j < 4; j++) sf0[i][j] = 0.f;
#pragma unroll
    for (int kb = 0; kb < 6; kb++) {
        const uint32_t koff = (kb*16 + bkh) * 2;
#pragma unroll
        for (int nt = 0; nt < 2; nt++) {
            uint32_t t4[4];
            ldm4(t4, kbase + (nt*16 + brow) * KSTRB + koff);
            mma16816(sf0[2*nt],   qa[kb], t4);
            mma16816(sf0[2*nt+1], qa[kb], t4+2);
        }
    }
    if (needmask) {
#pragma unroll
        for (int ni = 0; ni < 4; ni++) {
            const int c0 = j0e + ni*8 + ((lane & 3) << 1);
            if (c0     > grow0) sf0[ni][0] = -60000.f;
            if (c0 + 1 > grow0) sf0[ni][1] = -60000.f;
            if (c0     > grow1) sf0[ni][2] = -60000.f;
            if (c0 + 1 > grow1) sf0[ni][3] = -60000.f;
        }
    }
    uint32_t p0[2][4];
#pragma unroll
    for (int kb2 = 0; kb2 < 2; kb2++)
#pragma unroll
        for (int g = 0; g < 2; g++) {
            const float* p = sf0[2*kb2 + g];
            p0[kb2][2*g]   = pex2(p[0], p[1]);
            p0[kb2][2*g+1] = pex2(p[2], p[3]);
        }

    float sf1[4][4];
#pragma unroll
    for (int i = 0; i < 4; i++)
#pragma unroll
        for (int j = 0; j < 4; j++) sf1[i][j] = 0.f;
#pragma unroll
    for (int kb = 0; kb < 6; kb++) {
        const uint32_t koff = (kb*16 + bkh) * 2;
#pragma unroll
        for (int nt = 0; nt < 2; nt++) {
            uint32_t t4[4];
            ldm4(t4, kbase + ((nt+2)*16 + brow) * KSTRB + koff);
            mma16816(sf1[2*nt],   qa[kb], t4);
            mma16816(sf1[2*nt+1], qa[kb], t4+2);
        }
    }

#pragma unroll
    for (int kb2 = 0; kb2 < 2; kb2++) {
        const uint32_t vrow = vbase + (kb2*16 + jrow0) * VSTRB;
#pragma unroll
        for (int nt = 0; nt < 6; nt++) {
            uint32_t tv[4];
            ldm4t(tv, vrow + (nt*16 + dhalf) * 2);
            mma16816(o[2*nt],   p0[kb2], tv);
            mma16816(o[2*nt+1], p0[kb2], tv+2);
        }
        mma16816(o[12], p0[kb2], tvONE);
    }

    if (needmask) {
#pragma unroll
        for (int ni = 0; ni < 4; ni++) {
            const int c0 = j0e + 32 + ni*8 + ((lane & 3) << 1);
            if (c0     > grow0) sf1[ni][0] = -60000.f;
            if (c0 + 1 > grow0) sf1[ni][1] = -60000.f;
            if (c0     > grow1) sf1[ni][2] = -60000.f;
            if (c0 + 1 > grow1) sf1[ni][3] = -60000.f;
        }
    }
    uint32_t p1[2][4];
#pragma unroll
    for (int kb2 = 0; kb2 < 2; kb2++)
#pragma unroll
        for (int g = 0; g < 2; g++) {
            const float* p = sf1[2*kb2 + g];
            p1[kb2][2*g]   = pex2(p[0], p[1]);
            p1[kb2][2*g+1] = pex2(p[2], p[3]);
        }
#pragma unroll
    for (int kb2 = 0; kb2 < 2; kb2++) {
        const uint32_t vrow = vbase + ((kb2+2)*16 + jrow0) * VSTRB;
#pragma unroll
        for (int nt = 0; nt < 6; nt++) {
            uint32_t tv[4];
            ldm4t(tv, vrow + (nt*16 + dhalf) * 2);
            mma16816(o[2*nt],   p1[kb2], tv);
            mma16816(o[2*nt+1], p1[kb2], tv+2);
        }
        mma16816(o[12], p1[kb2], tvONE);
    }
}

__global__ __launch_bounds__(ATHR, 1) void attn_mma()
{
    extern __shared__ char dsm[];
    const uint32_t sb = cvta_smem(dsm);
    const uint32_t mb = sb + NSTAGE*ASTAGE;
    const int tid  = threadIdx.x;
    const int wid  = tid >> 5;
    const int lane = tid & 31;
    const int qt   = (int)gridDim.x - 1 - (int)blockIdx.x;
    const int bh   = blockIdx.y;
    const int qi0  = qt * BQ;
    const int njt  = (qi0 + BQ) / BK;
    const size_t gbase = (size_t)bh * T_ * HS_;

    {
#pragma unroll
        for (int i = 0; i < 6; i++) {
            const int idx = tid + i * ATHR;
            const int r = idx / 12;
            const int seg = idx - r * 12;
            CP16(sb + r * KSTRB + seg * 16,
                 g_q + gbase + (size_t)(qi0 + r) * HS_ + seg * 8);
        }
        CP_COMMIT(); CP_WAIT0();
    }
    __syncthreads();

    uint32_t qa[6][4];
    {
        const int arow = lane & 15;
        const int akh  = (lane >> 4) << 3;
#pragma unroll
        for (int kb = 0; kb < 6; kb++) {
            uint32_t ra = sb + (wid*16 + arow) * KSTRB + (kb*16 + akh) * 2;
            ldm4(qa[kb], ra);
        }
    }
    __syncthreads();

    if (tid == 0) {
#pragma unroll
        for (int s = 0; s < NSTAGE; s++) {
            MBAR_INIT(mb + s*16,     ATHR);
            MBAR_INIT(mb + s*16 + 8, NW);
        }
    }
    if (tid < 16) {
        char* vp = dsm + KTB + tid * VSTRB + 192;
        *(uint4*)vp      = make_uint4(0x00003C00u, 0u, 0u, 0u);
        *(uint4*)(vp+16) = make_uint4(0u, 0u, 0u, 0u);
    }
    __syncthreads();

    const int brow = (lane & 7) + ((lane >> 4) << 3);
    const int bkh  = ((lane >> 3) & 1) << 3;
    const int rloc = lane >> 2;
    const int wbase = qi0 + wid*16;
    const int grow0 = wbase + rloc;
    const int grow1 = grow0 + 8;
    const int jrow0 = lane & 15;
    const int dhalf = (lane >> 4) << 3;

    uint32_t tvONE[4];
    ldm4t(tvONE, sb + KTB + jrow0 * VSTRB + (96 + dhalf) * 2);

    float o[13][4];
#pragma unroll
    for (int i = 0; i < 13; i++)
#pragma unroll
        for (int j = 0; j < 4; j++) o[i][j] = 0.f;

    int pst = 0, pph = 1;
    int cst = 0, cph = 0;

#pragma unroll
    for (int i = 0; i < PDIST; i++) {
        if (i < njt) {
            MBAR_WAIT(mb + pst*16 + 8, pph);
            issue_att_nb(sb, pst, gbase, i * BK, tid);
            CPMB_ARRIVE(mb + pst*16);
            if (++pst == NSTAGE) { pst = 0; pph ^= 1; }
        }
    }

    for (int jt = 0; jt < njt; jt++) {
        const int j0 = jt * BK;

        MBAR_WAIT(mb + cst*16, cph);

        if (jt + PDIST < njt) {
            MBAR_WAIT(mb + pst*16 + 8, pph);
            issue_att_nb(sb, pst, gbase, (jt + PDIST) * BK, tid);
            CPMB_ARRIVE(mb + pst*16);
            if (++pst == NSTAGE) { pst = 0; pph ^= 1; }
        }

        const uint32_t base = sb + cst * ASTAGE;
        consume64(base, base + KTB, j0,
                  wbase, grow0, grow1, lane, brow, bkh, jrow0, dhalf,
                  qa, tvONE, o);
        consume64(base + 64*KSTRB, base + KTB + 64*VSTRB, j0 + 64,
                  wbase, grow0, grow1, lane, brow, bkh, jrow0, dhalf,
                  qa, tvONE, o);

        __syncwarp();
        if (lane == 0) MBAR_ARRIVE(mb + cst*16 + 8);
        if (++cst == NSTAGE) { cst = 0; cph ^= 1; }
    }

    const int src = lane & ~3;
    const float l0 = __shfl_sync(0xffffffffu, o[12][0], src);
    const float l1 = __shfl_sync(0xffffffffu, o[12][2], src);

    const float inv0 = 1.f / (l0 + 1e-9f);
    const float inv1 = 1.f / (l1 + 1e-9f);
    const int bb = bh >> 3;
    const int h  = bh & 7;
    const int t0 = qi0 + wid*16 + rloc;
    const int t1 = t0 + 8;
    const int dcol = ((lane & 3) << 1);
#pragma unroll
    for (int nf = 0; nf < 12; nf++) {
        const int d = nf*8 + dcol;
        const size_t a0 = (size_t)(bb*T_ + t0) * C_ + h*HS_ + d;
        const size_t a1 = (size_t)(bb*T_ + t1) * C_ + h*HS_ + d;
        *(__half2*)(g_y + a0) = __halves2half2(__float2half_rn(o[nf][0]*inv0),
                                               __float2half_rn(o[nf][1]*inv0));
        *(__half2*)(g_y + a1) = __halves2half2(__float2half_rn(o[nf][2]*inv1),
                                               __float2half_rn(o[nf][3]*inv1));
    }
}

// ---------------------------------------------------------------------------
extern "C" void kernel_launch(void* const* d_in, const int* in_sizes, int n_in,
                              void* d_out, int out_size)
{
    const float* x      = (const float*)d_in[0];
    const float* W_attn = (const float*)d_in[1];
    const float* b_attn = (const float*)d_in[2];
    const float* W_proj = (const float*)d_in[3];
    const float* b_proj = (const float*)d_in[4];
    float* out = (float*)d_out;

    cudaFuncSetAttribute(gemm_mma<0>, cudaFuncAttributeMaxDynamicSharedMemorySize, GEMM_SMEM0);
    cudaFuncSetAttribute(gemm_mma<1>, cudaFuncAttributeMaxDynamicSharedMemorySize, GEMM_SMEM1);
    cudaFuncSetAttribute(attn_mma,    cudaFuncAttributeMaxDynamicSharedMemorySize, ATT_SMEM);

    cvt_all<<<XBLK + WBLK, 256>>>(x, W_attn, W_proj);

    gemm_mma<0><<<dim3(C3_/128, M_/128), 256, GEMM_SMEM0>>>(b_attn, nullptr);

    attn_mma<<<dim3(T_/BQ, B_*H_), ATHR, ATT_SMEM>>>();

    gemm_mma<1><<<dim3(C_/64, M_/128), 256, GEMM_SMEM1>>>(b_proj, out);
}